// round 3
// baseline (speedup 1.0000x reference)
#include <cuda_runtime.h>

// Problem shapes (fixed by reference setup_inputs)
#define NB 32
#define NM 128
#define NN 64
#define ND 256
#define GROUP_M 8                 // m's per CTA in sim kernel
#define ROW_F4 (ND / 4)           // 64 float4 per row
#define TILE_F4 (NN * ND / 4)     // 4096 float4 per (b,m) tile

constexpr float EPS_F   = 1e-8f;
constexpr float NEG_BIG = -9e15f;

// Scratch (device globals per allocation rules)
__device__ float g_avg[NB * NM];
__device__ int   g_sel[NB];       // selected m index, or -1 if v <= 0.5

__device__ __forceinline__ float warp_sum(float v) {
    #pragma unroll
    for (int o = 16; o > 0; o >>= 1)
        v += __shfl_xor_sync(0xffffffffu, v, o);
    return v;
}

// ---------------------------------------------------------------------------
// Kernel 1: sim. Grid (16 groups, 32 batches), 1024 threads = 32 warps.
// Warp w owns rows n = 2w, 2w+1. It loads its dia rows ONCE into registers
// (16 floats/lane) and precomputes their norms, then streams GROUP_M=8 dd
// tiles against them. dd is read once from DRAM via __ldcs (evict-first);
// dia L2 traffic shrinks 8x vs one-CTA-per-(b,m).
// ---------------------------------------------------------------------------
__global__ void __launch_bounds__(1024, 1)
sim_kernel(const float* __restrict__ dia, const float* __restrict__ dd)
{
    const int g    = blockIdx.x;        // 0..15
    const int b    = blockIdx.y;        // 0..31
    const int warp = threadIdx.x >> 5;  // 0..31
    const int lane = threadIdx.x & 31;

    const float4* __restrict__ dia4 =
        reinterpret_cast<const float4*>(dia) + (size_t)b * TILE_F4;
    const float4* __restrict__ dd4 =
        reinterpret_cast<const float4*>(dd) +
        ((size_t)b * NM + (size_t)g * GROUP_M) * TILE_F4;

    // --- dia rows for this warp, register-resident, plus norms ---
    float4 q[2][2];
    float  qn[2];
    #pragma unroll
    for (int r = 0; r < 2; ++r) {
        const int n = warp * 2 + r;
        q[r][0] = dia4[n * ROW_F4 + lane];
        q[r][1] = dia4[n * ROW_F4 + 32 + lane];
        float qs = 0.f;
        qs = fmaf(q[r][0].x, q[r][0].x, qs); qs = fmaf(q[r][0].y, q[r][0].y, qs);
        qs = fmaf(q[r][0].z, q[r][0].z, qs); qs = fmaf(q[r][0].w, q[r][0].w, qs);
        qs = fmaf(q[r][1].x, q[r][1].x, qs); qs = fmaf(q[r][1].y, q[r][1].y, qs);
        qs = fmaf(q[r][1].z, q[r][1].z, qs); qs = fmaf(q[r][1].w, q[r][1].w, qs);
        qn[r] = sqrtf(warp_sum(qs));
    }

    float    psum[GROUP_M];
    unsigned cpack = 0;                 // 4 bits per m (count of non-pad rows, <=2)
    #pragma unroll
    for (int mi = 0; mi < GROUP_M; ++mi) psum[mi] = 0.f;

    for (int mi = 0; mi < GROUP_M; ++mi) {
        const float4* __restrict__ tile = dd4 + (size_t)mi * TILE_F4;
        #pragma unroll
        for (int r = 0; r < 2; ++r) {
            const int n = warp * 2 + r;
            const float4 a0 = __ldcs(tile + n * ROW_F4 + lane);
            const float4 a1 = __ldcs(tile + n * ROW_F4 + 32 + lane);

            float dot = 0.f, dsq = 0.f, dab = 0.f;
            dot = fmaf(a0.x, q[r][0].x, dot); dot = fmaf(a0.y, q[r][0].y, dot);
            dot = fmaf(a0.z, q[r][0].z, dot); dot = fmaf(a0.w, q[r][0].w, dot);
            dot = fmaf(a1.x, q[r][1].x, dot); dot = fmaf(a1.y, q[r][1].y, dot);
            dot = fmaf(a1.z, q[r][1].z, dot); dot = fmaf(a1.w, q[r][1].w, dot);

            dsq = fmaf(a0.x, a0.x, dsq); dsq = fmaf(a0.y, a0.y, dsq);
            dsq = fmaf(a0.z, a0.z, dsq); dsq = fmaf(a0.w, a0.w, dsq);
            dsq = fmaf(a1.x, a1.x, dsq); dsq = fmaf(a1.y, a1.y, dsq);
            dsq = fmaf(a1.z, a1.z, dsq); dsq = fmaf(a1.w, a1.w, dsq);

            dab += fabsf(a0.x) + fabsf(a0.y) + fabsf(a0.z) + fabsf(a0.w);
            dab += fabsf(a1.x) + fabsf(a1.y) + fabsf(a1.z) + fabsf(a1.w);

            // three interleaved butterflies (independent chains pipeline)
            #pragma unroll
            for (int o = 16; o > 0; o >>= 1) {
                dot += __shfl_xor_sync(0xffffffffu, dot, o);
                dsq += __shfl_xor_sync(0xffffffffu, dsq, o);
                dab += __shfl_xor_sync(0xffffffffu, dab, o);
            }

            const float den = fmaxf(qn[r] * sqrtf(dsq), EPS_F);
            psum[mi] += dot / den;                 // padded row: dot==0 -> 0
            cpack    += (dab != 0.f) ? (1u << (mi * 4)) : 0u;
        }
    }

    // --- cross-warp reduce: 32 warps x GROUP_M partials ---
    __shared__ float s_sum[32][GROUP_M + 1];
    __shared__ float s_cnt[32][GROUP_M + 1];
    if (lane == 0) {
        #pragma unroll
        for (int mi = 0; mi < GROUP_M; ++mi) {
            s_sum[warp][mi] = psum[mi];
            s_cnt[warp][mi] = (float)((cpack >> (mi * 4)) & 15u);
        }
    }
    __syncthreads();

    if (warp < GROUP_M) {
        float v = warp_sum(s_sum[lane][warp]);
        float c = warp_sum(s_cnt[lane][warp]);
        if (lane == 0) {
            const float dn = (c == 0.f) ? NEG_BIG : c;
            g_avg[b * NM + g * GROUP_M + warp] = v / dn;
        }
    }
}

// ---------------------------------------------------------------------------
// Kernel 2: argmax over M=128 per batch; first-index tie-break.
// ---------------------------------------------------------------------------
__global__ void __launch_bounds__(128)
argmax_kernel()
{
    const int b    = blockIdx.x;
    const int tid  = threadIdx.x;
    const int warp = tid >> 5;
    const int lane = tid & 31;

    float v = g_avg[b * NM + tid];
    int   i = tid;
    #pragma unroll
    for (int o = 16; o > 0; o >>= 1) {
        const float ov = __shfl_xor_sync(0xffffffffu, v, o);
        const int   oi = __shfl_xor_sync(0xffffffffu, i, o);
        if (ov > v || (ov == v && oi < i)) { v = ov; i = oi; }
    }

    __shared__ float s_v[4];
    __shared__ int   s_i[4];
    if (lane == 0) { s_v[warp] = v; s_i[warp] = i; }
    __syncthreads();

    if (tid == 0) {
        float bv = s_v[0]; int bi = s_i[0];
        #pragma unroll
        for (int w = 1; w < 4; ++w) {
            if (s_v[w] > bv || (s_v[w] == bv && s_i[w] < bi)) { bv = s_v[w]; bi = s_i[w]; }
        }
        g_sel[b] = (bv > 0.5f) ? bi : -1;
    }
}

// ---------------------------------------------------------------------------
// Kernel 3: gather/blend copy, 1 float4 per thread, 512 CTAs.
// ---------------------------------------------------------------------------
__global__ void __launch_bounds__(256)
copy_kernel(const float* __restrict__ dia, const float* __restrict__ dd,
            float* __restrict__ out)
{
    const int idx = blockIdx.x * 256 + threadIdx.x;   // 0 .. NB*TILE_F4-1
    const int b   = idx >> 12;                        // TILE_F4 = 4096
    const int off = idx & (TILE_F4 - 1);
    const int sel = g_sel[b];

    const float4* __restrict__ src =
        (sel >= 0)
            ? reinterpret_cast<const float4*>(dd) +
              ((size_t)b * NM + sel) * TILE_F4 + off
            : reinterpret_cast<const float4*>(dia) + (size_t)b * TILE_F4 + off;

    reinterpret_cast<float4*>(out)[idx] = *src;
}

// ---------------------------------------------------------------------------
// Launch contract
// ---------------------------------------------------------------------------
extern "C" void kernel_launch(void* const* d_in, const int* in_sizes, int n_in,
                              void* d_out, int out_size)
{
    const float* dia = (const float*)d_in[0];
    const float* dd  = (const float*)d_in[1];
    if (n_in >= 2 && in_sizes[0] > in_sizes[1]) {  // defensive order check
        const float* t = dia; dia = dd; dd = t;
    }

    sim_kernel<<<dim3(NM / GROUP_M, NB), 1024>>>(dia, dd);
    argmax_kernel<<<NB, 128>>>();
    copy_kernel<<<(NB * TILE_F4) / 256, 256>>>(dia, dd, (float*)d_out);
}

// round 5
// speedup vs baseline: 1.1343x; 1.1343x over previous
#include <cuda_runtime.h>

// Problem shapes (fixed by reference setup_inputs)
#define NB 32
#define NM 128
#define NN 64
#define ND 256
#define GROUP_M 4                 // m's per CTA in sim kernel
#define ROW_F4 (ND / 4)           // 64 float4 per row
#define TILE_F4 (NN * ND / 4)     // 4096 float4 per (b,m) tile

constexpr float EPS_F   = 1e-8f;
constexpr float NEG_BIG = -9e15f;

// Scratch (device globals per allocation rules)
__device__ float g_avg[NB * NM];
__device__ int   g_sel[NB];       // selected m index, or -1 if v <= 0.5

// ---------------------------------------------------------------------------
// Kernel 1: sim. Grid (32 groups, 32 batches) = 1024 CTAs, 512 threads
// (16 warps, 2 CTAs/SM). Warp w owns rows n = 4w..4w+3. Prologue computes the
// 4 dia row norms once (kept as 4 scalars). Main loop streams GROUP_M=4 dd
// tiles; dia rows are re-read from L1 (tile is L1-resident, zero extra DRAM).
// Padding mask uses (dsq != 0)  [sum|x|==0  <=>  sum x^2 == 0], eliminating
// the third warp reduction and all abs ops.
// ---------------------------------------------------------------------------
__global__ void __launch_bounds__(512, 2)
sim_kernel(const float* __restrict__ dia, const float* __restrict__ dd)
{
    const int g    = blockIdx.x;        // 0..31
    const int b    = blockIdx.y;        // 0..31
    const int warp = threadIdx.x >> 5;  // 0..15
    const int lane = threadIdx.x & 31;

    const float4* __restrict__ dia4 =
        reinterpret_cast<const float4*>(dia) + (size_t)b * TILE_F4;
    const float4* __restrict__ dd4 =
        reinterpret_cast<const float4*>(dd) +
        ((size_t)b * NM + (size_t)g * GROUP_M) * TILE_F4;

    // --- prologue: dia row norms for this warp's 4 rows ---
    float qn[4];
    #pragma unroll
    for (int r = 0; r < 4; ++r) {
        const int n = warp * 4 + r;
        const float4 q0 = dia4[n * ROW_F4 + lane];
        const float4 q1 = dia4[n * ROW_F4 + 32 + lane];
        float qs = 0.f;
        qs = fmaf(q0.x, q0.x, qs); qs = fmaf(q0.y, q0.y, qs);
        qs = fmaf(q0.z, q0.z, qs); qs = fmaf(q0.w, q0.w, qs);
        qs = fmaf(q1.x, q1.x, qs); qs = fmaf(q1.y, q1.y, qs);
        qs = fmaf(q1.z, q1.z, qs); qs = fmaf(q1.w, q1.w, qs);
        #pragma unroll
        for (int o = 16; o > 0; o >>= 1)
            qs += __shfl_xor_sync(0xffffffffu, qs, o);
        qn[r] = sqrtf(qs);
    }

    float    psum[GROUP_M];
    unsigned cpack = 0;                 // 4 bits per mi: # non-padding rows (<=4)
    #pragma unroll
    for (int mi = 0; mi < GROUP_M; ++mi) psum[mi] = 0.f;

    #pragma unroll
    for (int mi = 0; mi < GROUP_M; ++mi) {
        const float4* __restrict__ tile = dd4 + (size_t)mi * TILE_F4;
        #pragma unroll
        for (int h = 0; h < 2; ++h) {   // two rows per step
            const int n0 = warp * 4 + h * 2;
            const int n1 = n0 + 1;

            // front-batch all 8 loads (4 dd via streaming hint, 4 dia L1-hot)
            const float4 a00 = __ldcs(tile + n0 * ROW_F4 + lane);
            const float4 a01 = __ldcs(tile + n0 * ROW_F4 + 32 + lane);
            const float4 a10 = __ldcs(tile + n1 * ROW_F4 + lane);
            const float4 a11 = __ldcs(tile + n1 * ROW_F4 + 32 + lane);
            const float4 q00 = dia4[n0 * ROW_F4 + lane];
            const float4 q01 = dia4[n0 * ROW_F4 + 32 + lane];
            const float4 q10 = dia4[n1 * ROW_F4 + lane];
            const float4 q11 = dia4[n1 * ROW_F4 + 32 + lane];

            float dot0 = 0.f, dsq0 = 0.f, dot1 = 0.f, dsq1 = 0.f;
            dot0 = fmaf(a00.x, q00.x, dot0); dot0 = fmaf(a00.y, q00.y, dot0);
            dot0 = fmaf(a00.z, q00.z, dot0); dot0 = fmaf(a00.w, q00.w, dot0);
            dot0 = fmaf(a01.x, q01.x, dot0); dot0 = fmaf(a01.y, q01.y, dot0);
            dot0 = fmaf(a01.z, q01.z, dot0); dot0 = fmaf(a01.w, q01.w, dot0);

            dsq0 = fmaf(a00.x, a00.x, dsq0); dsq0 = fmaf(a00.y, a00.y, dsq0);
            dsq0 = fmaf(a00.z, a00.z, dsq0); dsq0 = fmaf(a00.w, a00.w, dsq0);
            dsq0 = fmaf(a01.x, a01.x, dsq0); dsq0 = fmaf(a01.y, a01.y, dsq0);
            dsq0 = fmaf(a01.z, a01.z, dsq0); dsq0 = fmaf(a01.w, a01.w, dsq0);

            dot1 = fmaf(a10.x, q10.x, dot1); dot1 = fmaf(a10.y, q10.y, dot1);
            dot1 = fmaf(a10.z, q10.z, dot1); dot1 = fmaf(a10.w, q10.w, dot1);
            dot1 = fmaf(a11.x, q11.x, dot1); dot1 = fmaf(a11.y, q11.y, dot1);
            dot1 = fmaf(a11.z, q11.z, dot1); dot1 = fmaf(a11.w, q11.w, dot1);

            dsq1 = fmaf(a10.x, a10.x, dsq1); dsq1 = fmaf(a10.y, a10.y, dsq1);
            dsq1 = fmaf(a10.z, a10.z, dsq1); dsq1 = fmaf(a10.w, a10.w, dsq1);
            dsq1 = fmaf(a11.x, a11.x, dsq1); dsq1 = fmaf(a11.y, a11.y, dsq1);
            dsq1 = fmaf(a11.w, a11.w, dsq1); dsq1 = fmaf(a11.z, a11.z, dsq1);

            // four interleaved butterflies (independent chains pipeline)
            #pragma unroll
            for (int o = 16; o > 0; o >>= 1) {
                dot0 += __shfl_xor_sync(0xffffffffu, dot0, o);
                dsq0 += __shfl_xor_sync(0xffffffffu, dsq0, o);
                dot1 += __shfl_xor_sync(0xffffffffu, dot1, o);
                dsq1 += __shfl_xor_sync(0xffffffffu, dsq1, o);
            }

            const float den0 = fmaxf(qn[h * 2]     * sqrtf(dsq0), EPS_F);
            const float den1 = fmaxf(qn[h * 2 + 1] * sqrtf(dsq1), EPS_F);
            psum[mi] += dot0 / den0 + dot1 / den1;   // padded row: dot==0 -> 0
            cpack    += (unsigned)((dsq0 != 0.f) + (dsq1 != 0.f)) << (mi * 4);
        }
    }

    // --- cross-warp reduce: 16 warps x GROUP_M partials ---
    __shared__ float s_sum[16][GROUP_M + 1];
    __shared__ float s_cnt[16][GROUP_M + 1];
    if (lane == 0) {
        #pragma unroll
        for (int mi = 0; mi < GROUP_M; ++mi) {
            s_sum[warp][mi] = psum[mi];
            s_cnt[warp][mi] = (float)((cpack >> (mi * 4)) & 15u);
        }
    }
    __syncthreads();

    // 64 threads: tid = mi*16 + widx; reduce within 16-lane xor groups
    if (threadIdx.x < 64) {
        const int mi  = threadIdx.x >> 4;
        const int wi  = threadIdx.x & 15;
        float v = s_sum[wi][mi];
        float c = s_cnt[wi][mi];
        #pragma unroll
        for (int o = 8; o > 0; o >>= 1) {
            v += __shfl_xor_sync(0xffffffffu, v, o);
            c += __shfl_xor_sync(0xffffffffu, c, o);
        }
        if (wi == 0) {
            const float dn = (c == 0.f) ? NEG_BIG : c;
            g_avg[b * NM + g * GROUP_M + mi] = v / dn;
        }
    }
}

// ---------------------------------------------------------------------------
// Kernel 2: argmax over M=128 per batch; first-index tie-break.
// ---------------------------------------------------------------------------
__global__ void __launch_bounds__(128)
argmax_kernel()
{
    const int b    = blockIdx.x;
    const int tid  = threadIdx.x;
    const int warp = tid >> 5;
    const int lane = tid & 31;

    float v = g_avg[b * NM + tid];
    int   i = tid;
    #pragma unroll
    for (int o = 16; o > 0; o >>= 1) {
        const float ov = __shfl_xor_sync(0xffffffffu, v, o);
        const int   oi = __shfl_xor_sync(0xffffffffu, i, o);
        if (ov > v || (ov == v && oi < i)) { v = ov; i = oi; }
    }

    __shared__ float s_v[4];
    __shared__ int   s_i[4];
    if (lane == 0) { s_v[warp] = v; s_i[warp] = i; }
    __syncthreads();

    if (tid == 0) {
        float bv = s_v[0]; int bi = s_i[0];
        #pragma unroll
        for (int w = 1; w < 4; ++w) {
            if (s_v[w] > bv || (s_v[w] == bv && s_i[w] < bi)) { bv = s_v[w]; bi = s_i[w]; }
        }
        g_sel[b] = (bv > 0.5f) ? bi : -1;
    }
}

// ---------------------------------------------------------------------------
// Kernel 3: gather/blend copy, 1 float4 per thread, 512 CTAs.
// ---------------------------------------------------------------------------
__global__ void __launch_bounds__(256)
copy_kernel(const float* __restrict__ dia, const float* __restrict__ dd,
            float* __restrict__ out)
{
    const int idx = blockIdx.x * 256 + threadIdx.x;   // 0 .. NB*TILE_F4-1
    const int b   = idx >> 12;                        // TILE_F4 = 4096
    const int off = idx & (TILE_F4 - 1);
    const int sel = g_sel[b];

    const float4* __restrict__ src =
        (sel >= 0)
            ? reinterpret_cast<const float4*>(dd) +
              ((size_t)b * NM + sel) * TILE_F4 + off
            : reinterpret_cast<const float4*>(dia) + (size_t)b * TILE_F4 + off;

    reinterpret_cast<float4*>(out)[idx] = *src;
}

// ---------------------------------------------------------------------------
// Launch contract
// ---------------------------------------------------------------------------
extern "C" void kernel_launch(void* const* d_in, const int* in_sizes, int n_in,
                              void* d_out, int out_size)
{
    const float* dia = (const float*)d_in[0];
    const float* dd  = (const float*)d_in[1];
    if (n_in >= 2 && in_sizes[0] > in_sizes[1]) {  // defensive order check
        const float* t = dia; dia = dd; dd = t;
    }

    sim_kernel<<<dim3(NM / GROUP_M, NB), 512>>>(dia, dd);
    argmax_kernel<<<NB, 128>>>();
    copy_kernel<<<(NB * TILE_F4) / 256, 256>>>(dia, dd, (float*)d_out);
}

// round 6
// speedup vs baseline: 1.3484x; 1.1887x over previous
#include <cuda_runtime.h>

// Problem shapes (fixed by reference setup_inputs)
#define NB 32
#define NM 128
#define NN 64
#define ND 256
#define GROUP_M 2                 // tiles (m) per CTA in sim kernel
#define ROW_F4 (ND / 4)           // 64 float4 per row
#define TILE_F4 (NN * ND / 4)     // 4096 float4 per (b,m) tile

constexpr float EPS_F   = 1e-8f;
constexpr float NEG_BIG = -9e15f;

// Scratch (device globals per allocation rules)
__device__ float g_qn[NB * NN];   // dia row norms
__device__ float g_avg[NB * NM];
__device__ int   g_sel[NB];       // selected m index, or -1 if v <= 0.5

// ---------------------------------------------------------------------------
// Kernel 0: dia row norms. One warp per (b,n) row; 2048 rows total.
// ---------------------------------------------------------------------------
__global__ void __launch_bounds__(256)
norm_kernel(const float* __restrict__ dia)
{
    const int row  = blockIdx.x * 8 + (threadIdx.x >> 5);  // 0..2047
    const int lane = threadIdx.x & 31;
    const float4* __restrict__ r4 =
        reinterpret_cast<const float4*>(dia) + (size_t)row * ROW_F4;

    const float4 q0 = r4[lane];
    const float4 q1 = r4[lane + 32];
    float qs = 0.f;
    qs = fmaf(q0.x, q0.x, qs); qs = fmaf(q0.y, q0.y, qs);
    qs = fmaf(q0.z, q0.z, qs); qs = fmaf(q0.w, q0.w, qs);
    qs = fmaf(q1.x, q1.x, qs); qs = fmaf(q1.y, q1.y, qs);
    qs = fmaf(q1.z, q1.z, qs); qs = fmaf(q1.w, q1.w, qs);
    #pragma unroll
    for (int o = 16; o > 0; o >>= 1)
        qs += __shfl_xor_sync(0xffffffffu, qs, o);
    if (lane == 0) g_qn[row] = sqrtf(qs);
}

// ---------------------------------------------------------------------------
// Kernel 1: sim. Grid (64 groups, 32 batches) = 2048 CTAs, 256 threads
// (8 warps, 5 CTAs/SM). Warp w owns rows n = 8w..8w+7 and both tiles of the
// group. Per h-step: rows n0,n1 for tiles t0,t1 -> 8 independent reduction
// values (dot/dsq x 2 rows x 2 tiles) reduced with a SHARED butterfly:
//   3 xor steps on all 8 values (24 SHFL) -> each lane holds partials over
//   its (lane mod 4) residue class; lane group j = lane>>2 selects value j
//   (7 predicated SELs, no dynamic indexing); 2 xor steps within 4-lane
//   groups finish the sum; 1 more shuffle pairs dot with dsq.
// 27 shuffles per 4KB of dd (vs 40 naive). dia rows load once per h-step,
// reused in registers for both tiles. Row norms come precomputed from g_qn.
// Padding mask: row is padding iff dsq == 0 (sum|x|==0 <=> sum x^2==0).
// ---------------------------------------------------------------------------
__global__ void __launch_bounds__(256, 5)
sim_kernel(const float* __restrict__ dia, const float* __restrict__ dd)
{
    const int g    = blockIdx.x;        // 0..63
    const int b    = blockIdx.y;        // 0..31
    const int warp = threadIdx.x >> 5;  // 0..7
    const int lane = threadIdx.x & 31;

    const float4* __restrict__ dia4 =
        reinterpret_cast<const float4*>(dia) + (size_t)b * TILE_F4;
    const float4* __restrict__ t0 =
        reinterpret_cast<const float4*>(dd) +
        ((size_t)b * NM + (size_t)g * GROUP_M) * TILE_F4;
    const float4* __restrict__ t1 = t0 + TILE_F4;

    // precomputed dia row norms for this warp's 8 rows (broadcast loads)
    float qn[8];
    #pragma unroll
    for (int r = 0; r < 8; ++r)
        qn[r] = g_qn[b * NN + warp * 8 + r];

    float psum_local = 0.f;   // per-lane: this lane's (tile,row-parity) slice
    float cnt_local  = 0.f;

    #pragma unroll
    for (int h = 0; h < 4; ++h) {
        const int n0 = warp * 8 + 2 * h;
        const int n1 = n0 + 1;

        // dia rows (L1-hot, reused for both tiles)
        const float4 q00 = dia4[n0 * ROW_F4 + lane];
        const float4 q01 = dia4[n0 * ROW_F4 + 32 + lane];
        const float4 q10 = dia4[n1 * ROW_F4 + lane];
        const float4 q11 = dia4[n1 * ROW_F4 + 32 + lane];
        // dd tile 0 rows (streaming)
        const float4 a00 = __ldcs(t0 + n0 * ROW_F4 + lane);
        const float4 a01 = __ldcs(t0 + n0 * ROW_F4 + 32 + lane);
        const float4 a10 = __ldcs(t0 + n1 * ROW_F4 + lane);
        const float4 a11 = __ldcs(t0 + n1 * ROW_F4 + 32 + lane);

        float v0 = 0.f, v1 = 0.f, v4 = 0.f, v5 = 0.f;
        v0 = fmaf(a00.x, q00.x, v0); v0 = fmaf(a00.y, q00.y, v0);
        v0 = fmaf(a00.z, q00.z, v0); v0 = fmaf(a00.w, q00.w, v0);
        v0 = fmaf(a01.x, q01.x, v0); v0 = fmaf(a01.y, q01.y, v0);
        v0 = fmaf(a01.z, q01.z, v0); v0 = fmaf(a01.w, q01.w, v0);
        v1 = fmaf(a00.x, a00.x, v1); v1 = fmaf(a00.y, a00.y, v1);
        v1 = fmaf(a00.z, a00.z, v1); v1 = fmaf(a00.w, a00.w, v1);
        v1 = fmaf(a01.x, a01.x, v1); v1 = fmaf(a01.y, a01.y, v1);
        v1 = fmaf(a01.z, a01.z, v1); v1 = fmaf(a01.w, a01.w, v1);
        v4 = fmaf(a10.x, q10.x, v4); v4 = fmaf(a10.y, q10.y, v4);
        v4 = fmaf(a10.z, q10.z, v4); v4 = fmaf(a10.w, q10.w, v4);
        v4 = fmaf(a11.x, q11.x, v4); v4 = fmaf(a11.y, q11.y, v4);
        v4 = fmaf(a11.z, q11.z, v4); v4 = fmaf(a11.w, q11.w, v4);
        v5 = fmaf(a10.x, a10.x, v5); v5 = fmaf(a10.y, a10.y, v5);
        v5 = fmaf(a10.z, a10.z, v5); v5 = fmaf(a10.w, a10.w, v5);
        v5 = fmaf(a11.x, a11.x, v5); v5 = fmaf(a11.y, a11.y, v5);
        v5 = fmaf(a11.z, a11.z, v5); v5 = fmaf(a11.w, a11.w, v5);

        // dd tile 1 rows
        const float4 b00 = __ldcs(t1 + n0 * ROW_F4 + lane);
        const float4 b01 = __ldcs(t1 + n0 * ROW_F4 + 32 + lane);
        const float4 b10 = __ldcs(t1 + n1 * ROW_F4 + lane);
        const float4 b11 = __ldcs(t1 + n1 * ROW_F4 + 32 + lane);

        float v2 = 0.f, v3 = 0.f, v6 = 0.f, v7 = 0.f;
        v2 = fmaf(b00.x, q00.x, v2); v2 = fmaf(b00.y, q00.y, v2);
        v2 = fmaf(b00.z, q00.z, v2); v2 = fmaf(b00.w, q00.w, v2);
        v2 = fmaf(b01.x, q01.x, v2); v2 = fmaf(b01.y, q01.y, v2);
        v2 = fmaf(b01.z, q01.z, v2); v2 = fmaf(b01.w, q01.w, v2);
        v3 = fmaf(b00.x, b00.x, v3); v3 = fmaf(b00.y, b00.y, v3);
        v3 = fmaf(b00.z, b00.z, v3); v3 = fmaf(b00.w, b00.w, v3);
        v3 = fmaf(b01.x, b01.x, v3); v3 = fmaf(b01.y, b01.y, v3);
        v3 = fmaf(b01.z, b01.z, v3); v3 = fmaf(b01.w, b01.w, v3);
        v6 = fmaf(b10.x, q10.x, v6); v6 = fmaf(b10.y, q10.y, v6);
        v6 = fmaf(b10.z, q10.z, v6); v6 = fmaf(b10.w, q10.w, v6);
        v6 = fmaf(b11.x, q11.x, v6); v6 = fmaf(b11.y, q11.y, v6);
        v6 = fmaf(b11.z, q11.z, v6); v6 = fmaf(b11.w, q11.w, v6);
        v7 = fmaf(b10.x, b10.x, v7); v7 = fmaf(b10.y, b10.y, v7);
        v7 = fmaf(b10.z, b10.z, v7); v7 = fmaf(b10.w, b10.w, v7);
        v7 = fmaf(b11.x, b11.x, v7); v7 = fmaf(b11.y, b11.y, v7);
        v7 = fmaf(b11.z, b11.z, v7); v7 = fmaf(b11.w, b11.w, v7);

        // shared butterfly: 3 steps on all 8 values
        #pragma unroll
        for (int o = 16; o >= 4; o >>= 1) {
            v0 += __shfl_xor_sync(0xffffffffu, v0, o);
            v1 += __shfl_xor_sync(0xffffffffu, v1, o);
            v2 += __shfl_xor_sync(0xffffffffu, v2, o);
            v3 += __shfl_xor_sync(0xffffffffu, v3, o);
            v4 += __shfl_xor_sync(0xffffffffu, v4, o);
            v5 += __shfl_xor_sync(0xffffffffu, v5, o);
            v6 += __shfl_xor_sync(0xffffffffu, v6, o);
            v7 += __shfl_xor_sync(0xffffffffu, v7, o);
        }
        // select value j = lane>>2 via predicated tree (no dynamic indexing)
        const bool s4  = (lane & 4)  != 0;
        const bool s8  = (lane & 8)  != 0;
        const bool s16 = (lane & 16) != 0;
        const float ta = s4 ? v1 : v0;
        const float tb = s4 ? v3 : v2;
        const float tc = s4 ? v5 : v4;
        const float td = s4 ? v7 : v6;
        const float ua = s8 ? tb : ta;
        const float ub = s8 ? td : tc;
        float w = s16 ? ub : ua;
        // finish: 2 steps within 4-lane groups
        w += __shfl_xor_sync(0xffffffffu, w, 1);
        w += __shfl_xor_sync(0xffffffffu, w, 2);
        // pair dot with dsq (adjacent 4-lane groups)
        const float other = __shfl_xor_sync(0xffffffffu, w, 4);
        const float dotv = s4 ? other : w;
        const float dsqv = s4 ? w : other;

        // lanes 0-7: (t0,n0); 8-15: (t1,n0); 16-23: (t0,n1); 24-31: (t1,n1)
        const float qnv = s16 ? qn[2 * h + 1] : qn[2 * h];
        const float den = fmaxf(qnv * sqrtf(dsqv), EPS_F);
        psum_local += __fdividef(dotv, den);     // padded row: dot==0 -> 0
        cnt_local  += (dsqv != 0.f) ? 1.f : 0.f;
    }

    // combine row-parity slices: lanes 0..15 then hold per-tile totals
    psum_local += __shfl_xor_sync(0xffffffffu, psum_local, 16);
    cnt_local  += __shfl_xor_sync(0xffffffffu, cnt_local, 16);

    __shared__ float s_sum[8][GROUP_M];
    __shared__ float s_cnt[8][GROUP_M];
    if (lane == 0 || lane == 8) {
        s_sum[warp][lane >> 3] = psum_local;
        s_cnt[warp][lane >> 3] = cnt_local;
    }
    __syncthreads();

    // 16 threads: ti = tid>>3 (tile), wi = tid&7 (warp); reduce over wi
    if (threadIdx.x < 16) {
        const int ti = threadIdx.x >> 3;
        const int wi = threadIdx.x & 7;
        float v = s_sum[wi][ti];
        float c = s_cnt[wi][ti];
        #pragma unroll
        for (int o = 4; o > 0; o >>= 1) {
            v += __shfl_xor_sync(0x0000ffffu, v, o);
            c += __shfl_xor_sync(0x0000ffffu, c, o);
        }
        if (wi == 0) {
            const float dn = (c == 0.f) ? NEG_BIG : c;
            g_avg[b * NM + g * GROUP_M + ti] = v / dn;
        }
    }
}

// ---------------------------------------------------------------------------
// Kernel 2: argmax over M=128 per batch; first-index tie-break.
// ---------------------------------------------------------------------------
__global__ void __launch_bounds__(128)
argmax_kernel()
{
    const int b    = blockIdx.x;
    const int tid  = threadIdx.x;
    const int warp = tid >> 5;
    const int lane = tid & 31;

    float v = g_avg[b * NM + tid];
    int   i = tid;
    #pragma unroll
    for (int o = 16; o > 0; o >>= 1) {
        const float ov = __shfl_xor_sync(0xffffffffu, v, o);
        const int   oi = __shfl_xor_sync(0xffffffffu, i, o);
        if (ov > v || (ov == v && oi < i)) { v = ov; i = oi; }
    }

    __shared__ float s_v[4];
    __shared__ int   s_i[4];
    if (lane == 0) { s_v[warp] = v; s_i[warp] = i; }
    __syncthreads();

    if (tid == 0) {
        float bv = s_v[0]; int bi = s_i[0];
        #pragma unroll
        for (int w = 1; w < 4; ++w) {
            if (s_v[w] > bv || (s_v[w] == bv && s_i[w] < bi)) { bv = s_v[w]; bi = s_i[w]; }
        }
        g_sel[b] = (bv > 0.5f) ? bi : -1;
    }
}

// ---------------------------------------------------------------------------
// Kernel 3: gather/blend copy, 1 float4 per thread, 512 CTAs.
// ---------------------------------------------------------------------------
__global__ void __launch_bounds__(256)
copy_kernel(const float* __restrict__ dia, const float* __restrict__ dd,
            float* __restrict__ out)
{
    const int idx = blockIdx.x * 256 + threadIdx.x;   // 0 .. NB*TILE_F4-1
    const int b   = idx >> 12;                        // TILE_F4 = 4096
    const int off = idx & (TILE_F4 - 1);
    const int sel = g_sel[b];

    const float4* __restrict__ src =
        (sel >= 0)
            ? reinterpret_cast<const float4*>(dd) +
              ((size_t)b * NM + sel) * TILE_F4 + off
            : reinterpret_cast<const float4*>(dia) + (size_t)b * TILE_F4 + off;

    reinterpret_cast<float4*>(out)[idx] = *src;
}

// ---------------------------------------------------------------------------
// Launch contract
// ---------------------------------------------------------------------------
extern "C" void kernel_launch(void* const* d_in, const int* in_sizes, int n_in,
                              void* d_out, int out_size)
{
    const float* dia = (const float*)d_in[0];
    const float* dd  = (const float*)d_in[1];
    if (n_in >= 2 && in_sizes[0] > in_sizes[1]) {  // defensive order check
        const float* t = dia; dia = dd; dd = t;
    }

    norm_kernel<<<NB * NN / 8, 256>>>(dia);
    sim_kernel<<<dim3(NM / GROUP_M, NB), 256>>>(dia, dd);
    argmax_kernel<<<NB, 128>>>();
    copy_kernel<<<(NB * TILE_F4) / 256, 256>>>(dia, dd, (float*)d_out);
}

// round 9
// speedup vs baseline: 1.3619x; 1.0100x over previous
#include <cuda_runtime.h>

// Problem shapes (fixed by reference setup_inputs)
#define NB 32
#define NM 128
#define NN 64
#define ND 256
#define GROUP_M 2                 // tiles (m) per CTA in sim kernel
#define ROW_F4 (ND / 4)           // 64 float4 per row
#define TILE_F4 (NN * ND / 4)     // 4096 float4 per (b,m) tile

constexpr float EPS_F   = 1e-8f;
constexpr float NEG_BIG = -9e15f;

// Scratch (device globals per allocation rules)
__device__ float g_qn[NB * NN];   // dia row norms
__device__ float g_avg[NB * NM];

// ---------------------------------------------------------------------------
// Kernel 0: dia row norms. One warp per (b,n) row; 2048 rows total.
// ---------------------------------------------------------------------------
__global__ void __launch_bounds__(256)
norm_kernel(const float* __restrict__ dia)
{
    const int row  = blockIdx.x * 8 + (threadIdx.x >> 5);  // 0..2047
    const int lane = threadIdx.x & 31;
    const float4* __restrict__ r4 =
        reinterpret_cast<const float4*>(dia) + (size_t)row * ROW_F4;

    const float4 q0 = r4[lane];
    const float4 q1 = r4[lane + 32];
    float qs = 0.f;
    qs = fmaf(q0.x, q0.x, qs); qs = fmaf(q0.y, q0.y, qs);
    qs = fmaf(q0.z, q0.z, qs); qs = fmaf(q0.w, q0.w, qs);
    qs = fmaf(q1.x, q1.x, qs); qs = fmaf(q1.y, q1.y, qs);
    qs = fmaf(q1.z, q1.z, qs); qs = fmaf(q1.w, q1.w, qs);
    #pragma unroll
    for (int o = 16; o > 0; o >>= 1)
        qs += __shfl_xor_sync(0xffffffffu, qs, o);
    if (lane == 0) g_qn[row] = sqrtf(qs);
}

// ---------------------------------------------------------------------------
// Kernel 1: sim. Grid (64 groups, 32 batches) = 2048 CTAs, 256 threads
// (8 warps, 5 CTAs/SM). Warp w owns rows n = 8w..8w+7 and both tiles of the
// group. Per h-step: rows n0,n1 for tiles t0,t1 -> 8 independent reduction
// values (dot/dsq x 2 rows x 2 tiles) reduced with a SHARED butterfly:
//   3 xor steps on all 8 values (24 SHFL) -> each lane holds partials over
//   its (lane mod 4) residue class; lane group j = lane>>2 selects value j
//   (7 predicated SELs, no dynamic indexing); 2 xor steps within 4-lane
//   groups finish the sum; 1 more shuffle pairs dot with dsq.
// 27 shuffles per 4KB of dd (vs 40 naive). dia rows load once per h-step,
// reused in registers for both tiles. Row norms come precomputed from g_qn.
// Padding mask: row is padding iff dsq == 0 (sum|x|==0 <=> sum x^2==0).
// ---------------------------------------------------------------------------
__global__ void __launch_bounds__(256, 5)
sim_kernel(const float* __restrict__ dia, const float* __restrict__ dd)
{
    const int g    = blockIdx.x;        // 0..63
    const int b    = blockIdx.y;        // 0..31
    const int warp = threadIdx.x >> 5;  // 0..7
    const int lane = threadIdx.x & 31;

    const float4* __restrict__ dia4 =
        reinterpret_cast<const float4*>(dia) + (size_t)b * TILE_F4;
    const float4* __restrict__ t0 =
        reinterpret_cast<const float4*>(dd) +
        ((size_t)b * NM + (size_t)g * GROUP_M) * TILE_F4;
    const float4* __restrict__ t1 = t0 + TILE_F4;

    // precomputed dia row norms for this warp's 8 rows (broadcast loads)
    float qn[8];
    #pragma unroll
    for (int r = 0; r < 8; ++r)
        qn[r] = g_qn[b * NN + warp * 8 + r];

    float psum_local = 0.f;   // per-lane: this lane's (tile,row-parity) slice
    float cnt_local  = 0.f;

    #pragma unroll
    for (int h = 0; h < 4; ++h) {
        const int n0 = warp * 8 + 2 * h;
        const int n1 = n0 + 1;

        // dia rows (L1-hot, reused for both tiles)
        const float4 q00 = dia4[n0 * ROW_F4 + lane];
        const float4 q01 = dia4[n0 * ROW_F4 + 32 + lane];
        const float4 q10 = dia4[n1 * ROW_F4 + lane];
        const float4 q11 = dia4[n1 * ROW_F4 + 32 + lane];
        // dd tile 0 rows (streaming)
        const float4 a00 = __ldcs(t0 + n0 * ROW_F4 + lane);
        const float4 a01 = __ldcs(t0 + n0 * ROW_F4 + 32 + lane);
        const float4 a10 = __ldcs(t0 + n1 * ROW_F4 + lane);
        const float4 a11 = __ldcs(t0 + n1 * ROW_F4 + 32 + lane);

        float v0 = 0.f, v1 = 0.f, v4 = 0.f, v5 = 0.f;
        v0 = fmaf(a00.x, q00.x, v0); v0 = fmaf(a00.y, q00.y, v0);
        v0 = fmaf(a00.z, q00.z, v0); v0 = fmaf(a00.w, q00.w, v0);
        v0 = fmaf(a01.x, q01.x, v0); v0 = fmaf(a01.y, q01.y, v0);
        v0 = fmaf(a01.z, q01.z, v0); v0 = fmaf(a01.w, q01.w, v0);
        v1 = fmaf(a00.x, a00.x, v1); v1 = fmaf(a00.y, a00.y, v1);
        v1 = fmaf(a00.z, a00.z, v1); v1 = fmaf(a00.w, a00.w, v1);
        v1 = fmaf(a01.x, a01.x, v1); v1 = fmaf(a01.y, a01.y, v1);
        v1 = fmaf(a01.z, a01.z, v1); v1 = fmaf(a01.w, a01.w, v1);
        v4 = fmaf(a10.x, q10.x, v4); v4 = fmaf(a10.y, q10.y, v4);
        v4 = fmaf(a10.z, q10.z, v4); v4 = fmaf(a10.w, q10.w, v4);
        v4 = fmaf(a11.x, q11.x, v4); v4 = fmaf(a11.y, q11.y, v4);
        v4 = fmaf(a11.z, q11.z, v4); v4 = fmaf(a11.w, q11.w, v4);
        v5 = fmaf(a10.x, a10.x, v5); v5 = fmaf(a10.y, a10.y, v5);
        v5 = fmaf(a10.z, a10.z, v5); v5 = fmaf(a10.w, a10.w, v5);
        v5 = fmaf(a11.x, a11.x, v5); v5 = fmaf(a11.y, a11.y, v5);
        v5 = fmaf(a11.w, a11.w, v5); v5 = fmaf(a11.z, a11.z, v5);

        // dd tile 1 rows
        const float4 b00 = __ldcs(t1 + n0 * ROW_F4 + lane);
        const float4 b01 = __ldcs(t1 + n0 * ROW_F4 + 32 + lane);
        const float4 b10 = __ldcs(t1 + n1 * ROW_F4 + lane);
        const float4 b11 = __ldcs(t1 + n1 * ROW_F4 + 32 + lane);

        float v2 = 0.f, v3 = 0.f, v6 = 0.f, v7 = 0.f;
        v2 = fmaf(b00.x, q00.x, v2); v2 = fmaf(b00.y, q00.y, v2);
        v2 = fmaf(b00.z, q00.z, v2); v2 = fmaf(b00.w, q00.w, v2);
        v2 = fmaf(b01.x, q01.x, v2); v2 = fmaf(b01.y, q01.y, v2);
        v2 = fmaf(b01.z, q01.z, v2); v2 = fmaf(b01.w, q01.w, v2);
        v3 = fmaf(b00.x, b00.x, v3); v3 = fmaf(b00.y, b00.y, v3);
        v3 = fmaf(b00.z, b00.z, v3); v3 = fmaf(b00.w, b00.w, v3);
        v3 = fmaf(b01.x, b01.x, v3); v3 = fmaf(b01.y, b01.y, v3);
        v3 = fmaf(b01.z, b01.z, v3); v3 = fmaf(b01.w, b01.w, v3);
        v6 = fmaf(b10.x, q10.x, v6); v6 = fmaf(b10.y, q10.y, v6);
        v6 = fmaf(b10.z, q10.z, v6); v6 = fmaf(b10.w, q10.w, v6);
        v6 = fmaf(b11.x, q11.x, v6); v6 = fmaf(b11.y, q11.y, v6);
        v6 = fmaf(b11.z, q11.z, v6); v6 = fmaf(b11.w, q11.w, v6);
        v7 = fmaf(b10.x, b10.x, v7); v7 = fmaf(b10.y, b10.y, v7);
        v7 = fmaf(b10.z, b10.z, v7); v7 = fmaf(b10.w, b10.w, v7);
        v7 = fmaf(b11.x, b11.x, v7); v7 = fmaf(b11.y, b11.y, v7);
        v7 = fmaf(b11.z, b11.z, v7); v7 = fmaf(b11.w, b11.w, v7);

        // shared butterfly: 3 steps on all 8 values
        #pragma unroll
        for (int o = 16; o >= 4; o >>= 1) {
            v0 += __shfl_xor_sync(0xffffffffu, v0, o);
            v1 += __shfl_xor_sync(0xffffffffu, v1, o);
            v2 += __shfl_xor_sync(0xffffffffu, v2, o);
            v3 += __shfl_xor_sync(0xffffffffu, v3, o);
            v4 += __shfl_xor_sync(0xffffffffu, v4, o);
            v5 += __shfl_xor_sync(0xffffffffu, v5, o);
            v6 += __shfl_xor_sync(0xffffffffu, v6, o);
            v7 += __shfl_xor_sync(0xffffffffu, v7, o);
        }
        // select value j = lane>>2 via predicated tree (no dynamic indexing)
        const bool s4  = (lane & 4)  != 0;
        const bool s8  = (lane & 8)  != 0;
        const bool s16 = (lane & 16) != 0;
        const float ta = s4 ? v1 : v0;
        const float tb = s4 ? v3 : v2;
        const float tc = s4 ? v5 : v4;
        const float td = s4 ? v7 : v6;
        const float ua = s8 ? tb : ta;
        const float ub = s8 ? td : tc;
        float w = s16 ? ub : ua;
        // finish: 2 steps within 4-lane groups
        w += __shfl_xor_sync(0xffffffffu, w, 1);
        w += __shfl_xor_sync(0xffffffffu, w, 2);
        // pair dot with dsq (adjacent 4-lane groups)
        const float other = __shfl_xor_sync(0xffffffffu, w, 4);
        const float dotv = s4 ? other : w;
        const float dsqv = s4 ? w : other;

        // lanes 0-7: (t0,n0); 8-15: (t1,n0); 16-23: (t0,n1); 24-31: (t1,n1)
        const float qnv = s16 ? qn[2 * h + 1] : qn[2 * h];
        const float den = fmaxf(qnv * sqrtf(dsqv), EPS_F);
        psum_local += __fdividef(dotv, den);     // padded row: dot==0 -> 0
        cnt_local  += (dsqv != 0.f) ? 1.f : 0.f;
    }

    // combine row-parity slices: lanes 0..15 then hold per-tile totals
    psum_local += __shfl_xor_sync(0xffffffffu, psum_local, 16);
    cnt_local  += __shfl_xor_sync(0xffffffffu, cnt_local, 16);

    __shared__ float s_sum[8][GROUP_M];
    __shared__ float s_cnt[8][GROUP_M];
    if (lane == 0 || lane == 8) {
        s_sum[warp][lane >> 3] = psum_local;
        s_cnt[warp][lane >> 3] = cnt_local;
    }
    __syncthreads();

    // 16 threads: ti = tid>>3 (tile), wi = tid&7 (warp); reduce over wi
    if (threadIdx.x < 16) {
        const int ti = threadIdx.x >> 3;
        const int wi = threadIdx.x & 7;
        float v = s_sum[wi][ti];
        float c = s_cnt[wi][ti];
        #pragma unroll
        for (int o = 4; o > 0; o >>= 1) {
            v += __shfl_xor_sync(0x0000ffffu, v, o);
            c += __shfl_xor_sync(0x0000ffffu, c, o);
        }
        if (wi == 0) {
            const float dn = (c == 0.f) ? NEG_BIG : c;
            g_avg[b * NM + g * GROUP_M + ti] = v / dn;
        }
    }
}

// ---------------------------------------------------------------------------
// Kernel 2: fused argmax + gather/blend copy. Grid = NB*8 = 256 CTAs of 512
// threads; each CTA covers 1/8 of its batch's output tile (512 float4).
// Each CTA redundantly computes the per-batch argmax from g_avg (128 L2-hot
// floats) -- cheaper than a separate dependent launch.
// ---------------------------------------------------------------------------
__global__ void __launch_bounds__(512)
out_kernel(const float* __restrict__ dia, const float* __restrict__ dd,
           float* __restrict__ out)
{
    const int b     = blockIdx.x >> 3;          // 0..31
    const int slice = blockIdx.x & 7;           // 0..7
    const int tid   = threadIdx.x;

    __shared__ float s_v[4];
    __shared__ int   s_i[4];
    __shared__ int   s_sel;

    // --- argmax over M=128 (first 128 threads), first-index tie-break ---
    if (tid < 128) {
        const int warp = tid >> 5;
        const int lane = tid & 31;
        float v = g_avg[b * NM + tid];
        int   i = tid;
        #pragma unroll
        for (int o = 16; o > 0; o >>= 1) {
            const float ov = __shfl_xor_sync(0xffffffffu, v, o);
            const int   oi = __shfl_xor_sync(0xffffffffu, i, o);
            if (ov > v || (ov == v && oi < i)) { v = ov; i = oi; }
        }
        if (lane == 0) { s_v[warp] = v; s_i[warp] = i; }
    }
    __syncthreads();
    if (tid == 0) {
        float bv = s_v[0]; int bi = s_i[0];
        #pragma unroll
        for (int w = 1; w < 4; ++w) {
            if (s_v[w] > bv || (s_v[w] == bv && s_i[w] < bi)) { bv = s_v[w]; bi = s_i[w]; }
        }
        s_sel = (bv > 0.5f) ? bi : -1;
    }
    __syncthreads();

    // --- copy this CTA's 512-float4 slice ---
    const int sel = s_sel;
    const int off = slice * 512 + tid;          // 0..4095 within the tile
    const float4* __restrict__ src =
        (sel >= 0)
            ? reinterpret_cast<const float4*>(dd) +
              ((size_t)b * NM + sel) * TILE_F4 + off
            : reinterpret_cast<const float4*>(dia) + (size_t)b * TILE_F4 + off;

    reinterpret_cast<float4*>(out)[(size_t)b * TILE_F4 + off] = *src;
}

// ---------------------------------------------------------------------------
// Launch contract
// ---------------------------------------------------------------------------
extern "C" void kernel_launch(void* const* d_in, const int* in_sizes, int n_in,
                              void* d_out, int out_size)
{
    const float* dia = (const float*)d_in[0];
    const float* dd  = (const float*)d_in[1];
    if (n_in >= 2 && in_sizes[0] > in_sizes[1]) {  // defensive order check
        const float* t = dia; dia = dd; dd = t;
    }

    norm_kernel<<<NB * NN / 8, 256>>>(dia);
    sim_kernel<<<dim3(NM / GROUP_M, NB), 256>>>(dia, dd);
    out_kernel<<<NB * 8, 512>>>(dia, dd, (float*)d_out);
}